// round 4
// baseline (speedup 1.0000x reference)
#include <cuda_runtime.h>

// CNN char conv + max-pool over word length.
// x: (N=B*S, W=20, E=128) fp32, contiguous.
// conv: 5-tap FIR along W with zero pad 2, + bias, then max over W.
// out: (N, E) fp32.
//
// Persistent grid + dynamic warp-granular work queue: each 32-thread warp
// owns one word at a time (32 lanes x float4 across E=128). The next word
// index is grabbed (atomicAdd by lane 0 + shfl) between the load batch and
// the compute tail, hiding the atomic's latency. This removes the 2-vs-3
// words/group static imbalance (util ceiling 92.3% -> ~99%).

#define WLEN 20
#define EV4  32   // 128 floats / 4 per float4

__device__ int g_word_counter;

__global__ void init_counter_kernel(int start) {
    g_word_counter = start;
}

__global__ __launch_bounds__(256, 5) void cnn_conv_max_kernel(
    const float* __restrict__ x,
    const float* __restrict__ w,
    const float* __restrict__ b,
    float* __restrict__ out,
    int n_words)
{
    const int lane_e = threadIdx.x & (EV4 - 1);

    // Weights/bias: 6 scalar loads, L1-resident after first iteration.
    const float w0 = w[0], w1 = w[1], w2 = w[2], w3 = w[3], w4 = w[4];
    const float bias = b[0];

    // First word is statically assigned: global warp id.
    int word = (blockIdx.x * blockDim.x + threadIdx.x) >> 5;

    while (word < n_words) {
        const float4* xw = reinterpret_cast<const float4*>(x)
                         + (size_t)word * (WLEN * EV4) + lane_e;

        // Independent coalesced loads; ptxas pipelines these (MLP ~10+).
        float4 xv[WLEN];
#pragma unroll
        for (int h = 0; h < WLEN; ++h) {
            xv[h] = xw[(size_t)h * EV4];
        }

        // Grab the next word while the loads are in flight / compute runs.
        int next;
        if (lane_e == 0) next = atomicAdd(&g_word_counter, 1);
        next = __shfl_sync(0xffffffffu, next, 0);

        float4 mx = make_float4(-3.4e38f, -3.4e38f, -3.4e38f, -3.4e38f);

#pragma unroll
        for (int h = 0; h < WLEN; ++h) {
            float ax = bias, ay = bias, az = bias, aw_ = bias;
#pragma unroll
            for (int k = 0; k < 5; ++k) {
                int idx = h + k - 2;            // zero pad of 2: skip OOB taps
                if (idx >= 0 && idx < WLEN) {   // compile-time resolvable
                    float wk = (k == 0) ? w0 : (k == 1) ? w1 : (k == 2) ? w2
                             : (k == 3) ? w3 : w4;
                    ax  = fmaf(wk, xv[idx].x, ax);
                    ay  = fmaf(wk, xv[idx].y, ay);
                    az  = fmaf(wk, xv[idx].z, az);
                    aw_ = fmaf(wk, xv[idx].w, aw_);
                }
            }
            mx.x = fmaxf(mx.x, ax);
            mx.y = fmaxf(mx.y, ay);
            mx.z = fmaxf(mx.z, az);
            mx.w = fmaxf(mx.w, aw_);
        }

        reinterpret_cast<float4*>(out)[(size_t)word * EV4 + lane_e] = mx;

        word = next;
    }
}

extern "C" void kernel_launch(void* const* d_in, const int* in_sizes, int n_in,
                              void* d_out, int out_size)
{
    const float* x = (const float*)d_in[0];   // (B,S,W,E)
    const float* w = (const float*)d_in[1];   // 5 floats
    const float* b = (const float*)d_in[2];   // 1 float

    int n_words = in_sizes[0] / (WLEN * 128); // B*S = 16384

    // Saturating persistent grid: 148 SMs x 5 blocks/SM, 8 warps/block.
    int block = 256;
    int grid  = 148 * 5;
    int max_grid = (n_words * EV4 + block - 1) / block;
    if (grid > max_grid) grid = max_grid;

    int n_static = grid * (block / 32);       // first-wave static assignments

    init_counter_kernel<<<1, 1>>>(n_static);
    cnn_conv_max_kernel<<<grid, block>>>(x, w, b, (float*)d_out, n_words);
}

// round 5
// speedup vs baseline: 1.1810x; 1.1810x over previous
#include <cuda_runtime.h>

// CNN char conv + max-pool over word length.
// x: (N=B*S, W=20, E=128) fp32, contiguous.
// conv: 5-tap FIR along W with zero pad 2, + bias, then max over W.
// out: (N, E) fp32.
//
// Persistent grid-stride (static): grid sized to exactly fill the chip
// (148 SMs x 5 blocks x 8 warps resident). Static stride keeps next-word
// addresses dependence-free so ptxas overlaps the next load batch with the
// current compute tail (the R4 atomic queue broke this and regressed).
// No cache hints: __ldcs measurably lowered DRAM% in R3 vs R2.

#define WLEN 20
#define EV4  32   // 128 floats / 4 per float4

__global__ __launch_bounds__(256, 5) void cnn_conv_max_kernel(
    const float* __restrict__ x,
    const float* __restrict__ w,
    const float* __restrict__ b,
    float* __restrict__ out,
    int n_words)
{
    const int lane_e = threadIdx.x & (EV4 - 1);
    const int group0 = (blockIdx.x * blockDim.x + threadIdx.x) >> 5;
    const int gstep  = (gridDim.x * blockDim.x) >> 5;

    // Weights/bias: 6 scalar loads, L1-resident after first iteration.
    const float w0 = w[0], w1 = w[1], w2 = w[2], w3 = w[3], w4 = w[4];
    const float bias = b[0];

    for (int word = group0; word < n_words; word += gstep) {
        const float4* xw = reinterpret_cast<const float4*>(x)
                         + (size_t)word * (WLEN * EV4) + lane_e;

        // Independent coalesced loads; ptxas pipelines these.
        float4 xv[WLEN];
#pragma unroll
        for (int h = 0; h < WLEN; ++h) {
            xv[h] = xw[(size_t)h * EV4];
        }

        float4 mx = make_float4(-3.4e38f, -3.4e38f, -3.4e38f, -3.4e38f);

#pragma unroll
        for (int h = 0; h < WLEN; ++h) {
            float ax = bias, ay = bias, az = bias, aw_ = bias;
#pragma unroll
            for (int k = 0; k < 5; ++k) {
                int idx = h + k - 2;            // zero pad of 2: skip OOB taps
                if (idx >= 0 && idx < WLEN) {   // compile-time resolvable
                    float wk = (k == 0) ? w0 : (k == 1) ? w1 : (k == 2) ? w2
                             : (k == 3) ? w3 : w4;
                    ax  = fmaf(wk, xv[idx].x, ax);
                    ay  = fmaf(wk, xv[idx].y, ay);
                    az  = fmaf(wk, xv[idx].z, az);
                    aw_ = fmaf(wk, xv[idx].w, aw_);
                }
            }
            mx.x = fmaxf(mx.x, ax);
            mx.y = fmaxf(mx.y, ay);
            mx.z = fmaxf(mx.z, az);
            mx.w = fmaxf(mx.w, aw_);
        }

        reinterpret_cast<float4*>(out)[(size_t)word * EV4 + lane_e] = mx;
    }
}

extern "C" void kernel_launch(void* const* d_in, const int* in_sizes, int n_in,
                              void* d_out, int out_size)
{
    const float* x = (const float*)d_in[0];   // (B,S,W,E)
    const float* w = (const float*)d_in[1];   // 5 floats
    const float* b = (const float*)d_in[2];   // 1 float

    int n_words = in_sizes[0] / (WLEN * 128); // B*S = 16384

    // Saturating persistent grid: 148 SMs x 5 blocks/SM.
    int block = 256;
    int grid  = 148 * 5;
    int max_grid = (n_words * EV4 + block - 1) / block;
    if (grid > max_grid) grid = max_grid;

    cnn_conv_max_kernel<<<grid, block>>>(x, w, b, (float*)d_out, n_words);
}